// round 16
// baseline (speedup 1.0000x reference)
#include <cuda_runtime.h>
#include <cuda_fp16.h>

#define NB   1024   // assets
#define NT   4096   // timesteps
#define NH   20     // hidden

__device__ float g_hlast[NB * NH];

using u64 = unsigned long long;

__device__ __forceinline__ u64 pack2(float lo, float hi) {
    u64 r;
    asm("mov.b64 %0, {%1, %2};" : "=l"(r)
        : "r"(__float_as_uint(lo)), "r"(__float_as_uint(hi)));
    return r;
}
__device__ __forceinline__ float2 unpack2(u64 v) {
    unsigned lo, hi;
    asm("mov.b64 {%0, %1}, %2;" : "=r"(lo), "=r"(hi) : "l"(v));
    return make_float2(__uint_as_float(lo), __uint_as_float(hi));
}
__device__ __forceinline__ u64 ffma2(u64 a, u64 b, u64 c) {
    u64 d;
    asm("fma.rn.f32x2 %0, %1, %2, %3;" : "=l"(d) : "l"(a), "l"(b), "l"(c));
    return d;
}
__device__ __forceinline__ float tanha(float x) {
    float y; asm("tanh.approx.f32 %0, %1;" : "=f"(y) : "f"(x)); return y;
}
__device__ __forceinline__ __half2 tanh2(__half2 v) {
    unsigned a = *reinterpret_cast<unsigned*>(&v), r;
    asm("tanh.approx.f16x2 %0, %1;" : "=r"(r) : "r"(a));
    return *reinterpret_cast<__half2*>(&r);
}

// ============================================================================
// R16 = R15 with the accumulator-clobbering stray line REMOVED.
// R5 schedule + HFMA2 rt-2 chains + ini folded into A-heads + packed f16x2
// epilogue. Chain coverage per slot: A = ini + k8 + k0,k2,k4,k6 ;
//                                    B =       k9 + k1,k3,k5,k7  (all 10 ks).
// 2 assets per warp; half = l>>4, q = l&15, asset = 2*bid + half.
// Lane q slots s=0..3: gate 20*s+q == unit q's i,f,g,o (lane-local).
// Slot s=4: gate 20*(q&3) + 16 + (q>>2)  (unit 16+(q>>2), type q&3).
// Sigmoid via 0.5*tanh(x/2)+0.5 (0.5 folded into weights); g-gate raw tanh.
// ============================================================================
__global__ void __launch_bounds__(32)
lstm_kernel(const float* __restrict__ x,
            const float* __restrict__ Wih,
            const float* __restrict__ Whh,
            const float* __restrict__ bih,
            const float* __restrict__ bhh)
{
    const int l  = threadIdx.x;
    const int q  = l & 15;
    const int hb = l & 16;
    const int half = l >> 4;
    const int asset = 2 * blockIdx.x + half;

    // h exchange in fp16: [buf][half][16 halves] = 32B per half per buf
    __shared__ __align__(16) __half s_h[2][2][16];

    // ---- per-slot constants ----
    __half2 wH[5][10];
    int gate[5];
#pragma unroll
    for (int s = 0; s < 4; s++) gate[s] = 20 * s + q;
    gate[4] = 20 * (q & 3) + 16 + (q >> 2);
    const bool t4 = ((q & 3) == 2);
    float sc[5];
#pragma unroll
    for (int s = 0; s < 5; s++) {
        const bool tg = (s == 2) || (s == 4 && t4);
        sc[s] = tg ? 1.0f : 0.5f;
        const float2* rw = reinterpret_cast<const float2*>(Whh + gate[s] * NH);
#pragma unroll
        for (int k = 0; k < 10; k++) {
            float2 v = rw[k];
            wH[s][k] = __floats2half2_rn(sc[s] * v.x, sc[s] * v.y);
        }
    }
    // ini weights: slot-pairs (0,1),(2,3),(4,-) packed f32x2
    u64 wiP0[3], wiP1[3], wiP2[3], biaP[3];
#pragma unroll
    for (int p = 0; p < 2; p++) {
        const int gA = gate[2*p], gB = gate[2*p+1];
        const float cA = sc[2*p], cB = sc[2*p+1];
        wiP0[p] = pack2(cA * Wih[gA*3+0], cB * Wih[gB*3+0]);
        wiP1[p] = pack2(cA * Wih[gA*3+1], cB * Wih[gB*3+1]);
        wiP2[p] = pack2(cA * Wih[gA*3+2], cB * Wih[gB*3+2]);
        biaP[p] = pack2(cA * (bih[gA] + bhh[gA]), cB * (bih[gB] + bhh[gB]));
    }
    {
        const int g4 = gate[4];
        wiP0[2] = pack2(sc[4] * Wih[g4*3+0], 0.f);
        wiP1[2] = pack2(sc[4] * Wih[g4*3+1], 0.f);
        wiP2[2] = pack2(sc[4] * Wih[g4*3+2], 0.f);
        biaP[2] = pack2(sc[4] * (bih[g4] + bhh[g4]), 0.f);
    }

    // activation fold constants (pairs: (i,f)=sigmoid, (g,o)=(tanh,sigmoid))
    const __half2 AA01 = __floats2half2_rn(0.5f, 0.5f);
    const __half2 AB01 = __floats2half2_rn(0.5f, 0.5f);
    const __half2 AA23 = __floats2half2_rn(1.0f, 0.5f);
    const __half2 AB23 = __floats2half2_rn(0.0f, 0.5f);
    const float aa4 = t4 ? 1.0f : 0.5f;
    const float ab4 = t4 ? 0.0f : 0.5f;
    const __half2 AA4 = __floats2half2_rn(aa4, aa4);
    const __half2 AB4 = __floats2half2_rn(ab4, ab4);

    // secondary gather sources: unit 16+q's type m comes from lane hb|(4q+m)
    const int sI = hb | ((4 * q + 0) & 15);
    const int sF = hb | ((4 * q + 1) & 15);
    const int sG = hb | ((4 * q + 2) & 15);
    const int sO = hb | ((4 * q + 3) & 15);

    // ---- x pointers: x[f][asset][t], float4 groups ----
    const float4* p0 = reinterpret_cast<const float4*>(x + (size_t)asset * NT);
    const float4* p1 = p0 + (size_t)NB * NT / 4;
    const float4* p2 = p1 + (size_t)NB * NT / 4;

    float4 cx0 = p0[0], cx1 = p1[0], cx2 = p2[0];

    __half2 hk[10];
    const __half2 Z2 = __floats2half2_rn(0.f, 0.f);
#pragma unroll
    for (int k = 0; k < 10; k++) hk[k] = Z2;
    float c1 = 0.f, c2 = 0.f, h1 = 0.f, h2 = 0.f;

    // first step's ini heads (bias + x-part of t=0): (ini, 0) half2 per slot
    __half2 iniH[5];
    {
        const u64 xx0 = pack2(cx0.x, cx0.x);
        const u64 xx1 = pack2(cx1.x, cx1.x);
        const u64 xx2 = pack2(cx2.x, cx2.x);
#pragma unroll
        for (int p = 0; p < 3; p++) {
            u64 ip = ffma2(xx0, wiP0[p],
                      ffma2(xx1, wiP1[p],
                       ffma2(xx2, wiP2[p], biaP[p])));
            float2 f = unpack2(ip);
            if (p < 2) {
                iniH[2*p]   = __floats2half2_rn(f.x, 0.f);
                iniH[2*p+1] = __floats2half2_rn(f.y, 0.f);
            } else {
                iniH[4] = __floats2half2_rn(f.x, 0.f);
            }
        }
    }

    // Xn* = x of the NEXT step (for the shadow init)
    auto step = [&](float Xn0, float Xn1, float Xn2, int buf) {
        // two 5-deep HFMA2 chains per slot; A-head carries ini, heads on
        // register-resident hk[8..9], then hk[0..7] in LDS arrival order
        __half2 a0, a1, a2, a3, a4, b0, b1, b2, b3, b4;
        a0 = __hfma2(hk[8], wH[0][8], iniH[0]);
        b0 = __hmul2(hk[9], wH[0][9]);
        a1 = __hfma2(hk[8], wH[1][8], iniH[1]);
        b1 = __hmul2(hk[9], wH[1][9]);
        a2 = __hfma2(hk[8], wH[2][8], iniH[2]);
        b2 = __hmul2(hk[9], wH[2][9]);
        a3 = __hfma2(hk[8], wH[3][8], iniH[3]);
        b3 = __hmul2(hk[9], wH[3][9]);
        a4 = __hfma2(hk[8], wH[4][8], iniH[4]);
        b4 = __hmul2(hk[9], wH[4][9]);
#pragma unroll
        for (int k = 0; k < 4; k++) {
            a0 = __hfma2(hk[2*k],   wH[0][2*k],   a0);
            b0 = __hfma2(hk[2*k+1], wH[0][2*k+1], b0);
            a1 = __hfma2(hk[2*k],   wH[1][2*k],   a1);
            b1 = __hfma2(hk[2*k+1], wH[1][2*k+1], b1);
            a2 = __hfma2(hk[2*k],   wH[2][2*k],   a2);
            b2 = __hfma2(hk[2*k+1], wH[2][2*k+1], b2);
            a3 = __hfma2(hk[2*k],   wH[3][2*k],   a3);
            b3 = __hfma2(hk[2*k+1], wH[3][2*k+1], b3);
            a4 = __hfma2(hk[2*k],   wH[4][2*k],   a4);
            b4 = __hfma2(hk[2*k+1], wH[4][2*k+1], b4);
        }
        // chains complete: A = ini+k8+k0,k2,k4,k6 ; B = k9+k1,k3,k5,k7

        // packed epilogue: pre = a.lo+a.hi+b.lo+b.hi per slot, pairs in f16x2
        const __half2 s0 = __hadd2(a0, b0);
        const __half2 s1 = __hadd2(a1, b1);
        const __half2 s2 = __hadd2(a2, b2);
        const __half2 s3 = __hadd2(a3, b3);
        const __half2 s4 = __hadd2(a4, b4);
        const __half2 D01 = __hadd2(__lows2half2(s0, s1), __highs2half2(s0, s1));
        const __half2 D23 = __hadd2(__lows2half2(s2, s3), __highs2half2(s2, s3));
        const __half2 D4  = __hadd2(__lows2half2(s4, s4), __highs2half2(s4, s4));
        const __half2 A01 = __hfma2(tanh2(D01), AA01, AB01);
        const __half2 A23 = __hfma2(tanh2(D23), AA23, AB23);
        const __half2 A4  = __hfma2(tanh2(D4),  AA4,  AB4);

        const float iA = __low2float(A01);
        const float fA = __high2float(A01);
        const float gA = __low2float(A23);
        const float oA = __high2float(A23);
        const float a4f = __low2float(A4);

        // secondary gather (register shuffles, off the primary path)
        const float i2 = __shfl_sync(0xffffffffu, a4f, sI);
        const float f2 = __shfl_sync(0xffffffffu, a4f, sF);
        const float g2 = __shfl_sync(0xffffffffu, a4f, sG);
        const float o2 = __shfl_sync(0xffffffffu, a4f, sO);

        // primary update: fully lane-local; h stored to smem as fp16
        c1 = fmaf(fA, c1, iA * gA);
        h1 = oA * tanha(c1);
        s_h[buf][half][q] = __float2half_rn(h1);

        // secondary update + distribution into hk[8..9] (inputs ready here)
        c2 = fmaf(f2, c2, i2 * g2);
        h2 = o2 * tanha(c2);
        hk[8] = __floats2half2_rn(__shfl_sync(0xffffffffu, h2, hb | 0),
                                  __shfl_sync(0xffffffffu, h2, hb | 1));
        hk[9] = __floats2half2_rn(__shfl_sync(0xffffffffu, h2, hb | 2),
                                  __shfl_sync(0xffffffffu, h2, hb | 3));

        // next step's ini heads in the sync shadow (fp32 -> (ini,0) half2)
        {
            const u64 xx0 = pack2(Xn0, Xn0);
            const u64 xx1 = pack2(Xn1, Xn1);
            const u64 xx2 = pack2(Xn2, Xn2);
#pragma unroll
            for (int p = 0; p < 3; p++) {
                u64 ip = ffma2(xx0, wiP0[p],
                          ffma2(xx1, wiP1[p],
                           ffma2(xx2, wiP2[p], biaP[p])));
                float2 f = unpack2(ip);
                if (p < 2) {
                    iniH[2*p]   = __floats2half2_rn(f.x, 0.f);
                    iniH[2*p+1] = __floats2half2_rn(f.y, 0.f);
                } else {
                    iniH[4] = __floats2half2_rn(f.x, 0.f);
                }
            }
        }

        __syncwarp();

        // hk[0..7] from smem (2x LDS.128 of fp16 h, broadcast, conflict-free)
        const uint4 r0 = *reinterpret_cast<const uint4*>(s_h[buf][half]);
        const uint4 r1 = *reinterpret_cast<const uint4*>(&s_h[buf][half][8]);
        hk[0] = *reinterpret_cast<const __half2*>(&r0.x);
        hk[1] = *reinterpret_cast<const __half2*>(&r0.y);
        hk[2] = *reinterpret_cast<const __half2*>(&r0.z);
        hk[3] = *reinterpret_cast<const __half2*>(&r0.w);
        hk[4] = *reinterpret_cast<const __half2*>(&r1.x);
        hk[5] = *reinterpret_cast<const __half2*>(&r1.y);
        hk[6] = *reinterpret_cast<const __half2*>(&r1.z);
        hk[7] = *reinterpret_cast<const __half2*>(&r1.w);
    };

#pragma unroll 1
    for (int t4i = 0; t4i < NT/4 - 1; t4i++) {
        const float4 nx0 = p0[t4i + 1];
        const float4 nx1 = p1[t4i + 1];
        const float4 nx2 = p2[t4i + 1];
        step(cx0.y, cx1.y, cx2.y, 0);
        step(cx0.z, cx1.z, cx2.z, 1);
        step(cx0.w, cx1.w, cx2.w, 0);
        step(nx0.x, nx1.x, nx2.x, 1);
        cx0 = nx0; cx1 = nx1; cx2 = nx2;
    }
    // last group: next-x args are don't-cares (reuse current)
    step(cx0.y, cx1.y, cx2.y, 0);
    step(cx0.z, cx1.z, cx2.z, 1);
    step(cx0.w, cx1.w, cx2.w, 0);
    step(cx0.w, cx1.w, cx2.w, 1);

    g_hlast[asset * NH + q] = h1;                 // units 0..15
    if (q < 4) g_hlast[asset * NH + 16 + q] = h2; // units 16..19
}

// head: fc + 1x1 conv compose linearly: z_b = cw0*la_b + relu(h_b)·u + s
__global__ void __launch_bounds__(NB)
head_kernel(const float* __restrict__ la,
            const float* __restrict__ fcw,
            const float* __restrict__ fcb,
            const float* __restrict__ cw,
            const float* __restrict__ cb,
            float* __restrict__ out)
{
    const int b = threadIdx.x;
    __shared__ float s_u[NH];
    __shared__ float s_s;
    __shared__ float s_red[32];
    __shared__ float s_bcast;

    if (b < NH) {
        float u = 0.f;
#pragma unroll
        for (int j = 0; j < NH; j++) u = fmaf(cw[1 + j], fcw[j * NH + b], u);
        s_u[b] = u;
    }
    if (b == NH) {
        float s = cb[0];
#pragma unroll
        for (int j = 0; j < NH; j++) s = fmaf(cw[1 + j], fcb[j], s);
        s_s = s;
    }
    __syncthreads();

    float z = fmaf(cw[0], la[b], s_s);
    const float* h = &g_hlast[b * NH];
#pragma unroll
    for (int j = 0; j < NH; j++) z = fmaf(fmaxf(h[j], 0.f), s_u[j], z);

    float m = z;
#pragma unroll
    for (int off = 16; off > 0; off >>= 1)
        m = fmaxf(m, __shfl_xor_sync(0xffffffffu, m, off));
    if ((b & 31) == 0) s_red[b >> 5] = m;
    __syncthreads();
    if (b < 32) {
        float v = s_red[b];
#pragma unroll
        for (int off = 16; off > 0; off >>= 1)
            v = fmaxf(v, __shfl_xor_sync(0xffffffffu, v, off));
        if (b == 0) s_bcast = fmaxf(v, 1.0f);
    }
    __syncthreads();
    m = s_bcast;

    float e = __expf(z - m);
    float s = e;
#pragma unroll
    for (int off = 16; off > 0; off >>= 1)
        s += __shfl_xor_sync(0xffffffffu, s, off);
    if ((b & 31) == 0) s_red[b >> 5] = s;
    __syncthreads();
    if (b < 32) {
        float v = s_red[b];
#pragma unroll
        for (int off = 16; off > 0; off >>= 1)
            v += __shfl_xor_sync(0xffffffffu, v, off);
        if (b == 0) s_bcast = v + __expf(1.0f - m);
    }
    __syncthreads();
    const float denom = s_bcast;

    out[1 + b] = e / denom;
    if (b == 0) out[0] = __expf(1.0f - m) / denom;
}

extern "C" void kernel_launch(void* const* d_in, const int* in_sizes, int n_in,
                              void* d_out, int out_size)
{
    const float* x   = (const float*)d_in[0];
    const float* la  = (const float*)d_in[1];
    const float* Wih = (const float*)d_in[2];
    const float* Whh = (const float*)d_in[3];
    const float* bih = (const float*)d_in[4];
    const float* bhh = (const float*)d_in[5];
    const float* fcw = (const float*)d_in[6];
    const float* fcb = (const float*)d_in[7];
    const float* cw  = (const float*)d_in[8];
    const float* cb  = (const float*)d_in[9];

    lstm_kernel<<<NB / 2, 32>>>(x, Wih, Whh, bih, bhh);
    head_kernel<<<1, NB>>>(la, fcw, fcb, cw, cb, (float*)d_out);
}

// round 17
// speedup vs baseline: 1.0834x; 1.0834x over previous
#include <cuda_runtime.h>
#include <cuda_fp16.h>

#define NB   1024   // assets
#define NT   4096   // timesteps
#define NH   20     // hidden

__device__ float g_hlast[NB * NH];

using u64 = unsigned long long;

__device__ __forceinline__ u64 pack2(float lo, float hi) {
    u64 r;
    asm("mov.b64 %0, {%1, %2};" : "=l"(r)
        : "r"(__float_as_uint(lo)), "r"(__float_as_uint(hi)));
    return r;
}
__device__ __forceinline__ float2 unpack2(u64 v) {
    unsigned lo, hi;
    asm("mov.b64 {%0, %1}, %2;" : "=r"(lo), "=r"(hi) : "l"(v));
    return make_float2(__uint_as_float(lo), __uint_as_float(hi));
}
__device__ __forceinline__ u64 ffma2(u64 a, u64 b, u64 c) {
    u64 d;
    asm("fma.rn.f32x2 %0, %1, %2, %3;" : "=l"(d) : "l"(a), "l"(b), "l"(c));
    return d;
}
__device__ __forceinline__ float tanha(float x) {
    float y; asm("tanh.approx.f32 %0, %1;" : "=f"(y) : "f"(x)); return y;
}

// ============================================================================
// R17 = R16 (correct fp16 chains, 626us) with the epilogue rebuilt:
// per-slot HADD2 + scalar half HADD + ONE F2F + fp32 tanh + fold.
// Slot-4 tail first (feeds the secondary gather earliest).
// Chains: HFMA2 rt-2; A = ini + k8 + k0,k2,k4,k6 ; B = k9 + k1,k3,k5,k7.
// 2 assets per warp; half = l>>4, q = l&15, asset = 2*bid + half.
// Lane q slots s=0..3: gate 20*s+q == unit q's i,f,g,o (lane-local).
// Slot s=4: gate 20*(q&3) + 16 + (q>>2)  (unit 16+(q>>2), type q&3).
// Sigmoid via 0.5*tanh(x/2)+0.5 (0.5 folded into weights); g-gate raw tanh.
// ============================================================================
__global__ void __launch_bounds__(32)
lstm_kernel(const float* __restrict__ x,
            const float* __restrict__ Wih,
            const float* __restrict__ Whh,
            const float* __restrict__ bih,
            const float* __restrict__ bhh)
{
    const int l  = threadIdx.x;
    const int q  = l & 15;
    const int hb = l & 16;
    const int half = l >> 4;
    const int asset = 2 * blockIdx.x + half;

    // h exchange in fp16: [buf][half][16 halves] = 32B per half per buf
    __shared__ __align__(16) __half s_h[2][2][16];

    // ---- per-slot constants ----
    __half2 wH[5][10];
    int gate[5];
#pragma unroll
    for (int s = 0; s < 4; s++) gate[s] = 20 * s + q;
    gate[4] = 20 * (q & 3) + 16 + (q >> 2);
    const bool t4 = ((q & 3) == 2);
    float sc[5];
#pragma unroll
    for (int s = 0; s < 5; s++) {
        const bool tg = (s == 2) || (s == 4 && t4);
        sc[s] = tg ? 1.0f : 0.5f;
        const float2* rw = reinterpret_cast<const float2*>(Whh + gate[s] * NH);
#pragma unroll
        for (int k = 0; k < 10; k++) {
            float2 v = rw[k];
            wH[s][k] = __floats2half2_rn(sc[s] * v.x, sc[s] * v.y);
        }
    }
    // ini weights: slot-pairs (0,1),(2,3),(4,-) packed f32x2
    u64 wiP0[3], wiP1[3], wiP2[3], biaP[3];
#pragma unroll
    for (int p = 0; p < 2; p++) {
        const int gA = gate[2*p], gB = gate[2*p+1];
        const float cA = sc[2*p], cB = sc[2*p+1];
        wiP0[p] = pack2(cA * Wih[gA*3+0], cB * Wih[gB*3+0]);
        wiP1[p] = pack2(cA * Wih[gA*3+1], cB * Wih[gB*3+1]);
        wiP2[p] = pack2(cA * Wih[gA*3+2], cB * Wih[gB*3+2]);
        biaP[p] = pack2(cA * (bih[gA] + bhh[gA]), cB * (bih[gB] + bhh[gB]));
    }
    {
        const int g4 = gate[4];
        wiP0[2] = pack2(sc[4] * Wih[g4*3+0], 0.f);
        wiP1[2] = pack2(sc[4] * Wih[g4*3+1], 0.f);
        wiP2[2] = pack2(sc[4] * Wih[g4*3+2], 0.f);
        biaP[2] = pack2(sc[4] * (bih[g4] + bhh[g4]), 0.f);
    }

    const float aa4 = t4 ? 1.0f : 0.5f;
    const float ab4 = t4 ? 0.0f : 0.5f;

    // secondary gather sources: unit 16+q's type m comes from lane hb|(4q+m)
    const int sI = hb | ((4 * q + 0) & 15);
    const int sF = hb | ((4 * q + 1) & 15);
    const int sG = hb | ((4 * q + 2) & 15);
    const int sO = hb | ((4 * q + 3) & 15);

    // ---- x pointers: x[f][asset][t], float4 groups ----
    const float4* p0 = reinterpret_cast<const float4*>(x + (size_t)asset * NT);
    const float4* p1 = p0 + (size_t)NB * NT / 4;
    const float4* p2 = p1 + (size_t)NB * NT / 4;

    float4 cx0 = p0[0], cx1 = p1[0], cx2 = p2[0];

    __half2 hk[10];
    const __half2 Z2 = __floats2half2_rn(0.f, 0.f);
#pragma unroll
    for (int k = 0; k < 10; k++) hk[k] = Z2;
    float c1 = 0.f, c2 = 0.f, h1 = 0.f, h2 = 0.f;

    // first step's ini heads (bias + x-part of t=0): (ini, 0) half2 per slot
    __half2 iniH[5];
    {
        const u64 xx0 = pack2(cx0.x, cx0.x);
        const u64 xx1 = pack2(cx1.x, cx1.x);
        const u64 xx2 = pack2(cx2.x, cx2.x);
#pragma unroll
        for (int p = 0; p < 3; p++) {
            u64 ip = ffma2(xx0, wiP0[p],
                      ffma2(xx1, wiP1[p],
                       ffma2(xx2, wiP2[p], biaP[p])));
            float2 f = unpack2(ip);
            if (p < 2) {
                iniH[2*p]   = __floats2half2_rn(f.x, 0.f);
                iniH[2*p+1] = __floats2half2_rn(f.y, 0.f);
            } else {
                iniH[4] = __floats2half2_rn(f.x, 0.f);
            }
        }
    }

    // Xn* = x of the NEXT step (for the shadow init)
    auto step = [&](float Xn0, float Xn1, float Xn2, int buf) {
        // two 5-deep HFMA2 chains per slot; A-head carries ini, heads on
        // register-resident hk[8..9], then hk[0..7] in LDS arrival order
        __half2 a0, a1, a2, a3, a4, b0, b1, b2, b3, b4;
        a4 = __hfma2(hk[8], wH[4][8], iniH[4]);
        b4 = __hmul2(hk[9], wH[4][9]);
        a0 = __hfma2(hk[8], wH[0][8], iniH[0]);
        b0 = __hmul2(hk[9], wH[0][9]);
        a1 = __hfma2(hk[8], wH[1][8], iniH[1]);
        b1 = __hmul2(hk[9], wH[1][9]);
        a2 = __hfma2(hk[8], wH[2][8], iniH[2]);
        b2 = __hmul2(hk[9], wH[2][9]);
        a3 = __hfma2(hk[8], wH[3][8], iniH[3]);
        b3 = __hmul2(hk[9], wH[3][9]);
#pragma unroll
        for (int k = 0; k < 4; k++) {
            a4 = __hfma2(hk[2*k],   wH[4][2*k],   a4);
            b4 = __hfma2(hk[2*k+1], wH[4][2*k+1], b4);
            a0 = __hfma2(hk[2*k],   wH[0][2*k],   a0);
            b0 = __hfma2(hk[2*k+1], wH[0][2*k+1], b0);
            a1 = __hfma2(hk[2*k],   wH[1][2*k],   a1);
            b1 = __hfma2(hk[2*k+1], wH[1][2*k+1], b1);
            a2 = __hfma2(hk[2*k],   wH[2][2*k],   a2);
            b2 = __hfma2(hk[2*k+1], wH[2][2*k+1], b2);
            a3 = __hfma2(hk[2*k],   wH[3][2*k],   a3);
            b3 = __hfma2(hk[2*k+1], wH[3][2*k+1], b3);
        }
        // chains complete: A = ini+k8+k0,k2,k4,k6 ; B = k9+k1,k3,k5,k7

        // per-slot epilogue: HADD2 + scalar half HADD + ONE F2F + fp32 tanh.
        // slot 4 first: its activation feeds the secondary gather.
        const __half2 S4 = __hadd2(a4, b4);
        const float pre4 = __half2float(__hadd(__low2half(S4), __high2half(S4)));
        const __half2 S0 = __hadd2(a0, b0);
        const __half2 S1 = __hadd2(a1, b1);
        const __half2 S2 = __hadd2(a2, b2);
        const __half2 S3 = __hadd2(a3, b3);
        const float a4f = fmaf(aa4, tanha(pre4), ab4);

        const float pre0 = __half2float(__hadd(__low2half(S0), __high2half(S0)));
        const float pre1 = __half2float(__hadd(__low2half(S1), __high2half(S1)));
        const float pre2 = __half2float(__hadd(__low2half(S2), __high2half(S2)));
        const float pre3 = __half2float(__hadd(__low2half(S3), __high2half(S3)));

        // secondary gather (inputs ready: a4f computed first)
        const float i2 = __shfl_sync(0xffffffffu, a4f, sI);
        const float f2 = __shfl_sync(0xffffffffu, a4f, sF);
        const float g2 = __shfl_sync(0xffffffffu, a4f, sG);
        const float o2 = __shfl_sync(0xffffffffu, a4f, sO);

        const float iA = fmaf(0.5f, tanha(pre0), 0.5f);
        const float fA = fmaf(0.5f, tanha(pre1), 0.5f);
        const float gA = tanha(pre2);
        const float oA = fmaf(0.5f, tanha(pre3), 0.5f);

        // primary update: fully lane-local; h stored to smem as fp16
        c1 = fmaf(fA, c1, iA * gA);
        h1 = oA * tanha(c1);
        s_h[buf][half][q] = __float2half_rn(h1);

        // secondary update + distribution into hk[8..9] (inputs ready here)
        c2 = fmaf(f2, c2, i2 * g2);
        h2 = o2 * tanha(c2);
        hk[8] = __floats2half2_rn(__shfl_sync(0xffffffffu, h2, hb | 0),
                                  __shfl_sync(0xffffffffu, h2, hb | 1));
        hk[9] = __floats2half2_rn(__shfl_sync(0xffffffffu, h2, hb | 2),
                                  __shfl_sync(0xffffffffu, h2, hb | 3));

        // next step's ini heads in the sync shadow (fp32 -> (ini,0) half2)
        {
            const u64 xx0 = pack2(Xn0, Xn0);
            const u64 xx1 = pack2(Xn1, Xn1);
            const u64 xx2 = pack2(Xn2, Xn2);
#pragma unroll
            for (int p = 0; p < 3; p++) {
                u64 ip = ffma2(xx0, wiP0[p],
                          ffma2(xx1, wiP1[p],
                           ffma2(xx2, wiP2[p], biaP[p])));
                float2 f = unpack2(ip);
                if (p < 2) {
                    iniH[2*p]   = __floats2half2_rn(f.x, 0.f);
                    iniH[2*p+1] = __floats2half2_rn(f.y, 0.f);
                } else {
                    iniH[4] = __floats2half2_rn(f.x, 0.f);
                }
            }
        }

        __syncwarp();

        // hk[0..7] from smem (2x LDS.128 of fp16 h, broadcast, conflict-free)
        const uint4 r0 = *reinterpret_cast<const uint4*>(s_h[buf][half]);
        const uint4 r1 = *reinterpret_cast<const uint4*>(&s_h[buf][half][8]);
        hk[0] = *reinterpret_cast<const __half2*>(&r0.x);
        hk[1] = *reinterpret_cast<const __half2*>(&r0.y);
        hk[2] = *reinterpret_cast<const __half2*>(&r0.z);
        hk[3] = *reinterpret_cast<const __half2*>(&r0.w);
        hk[4] = *reinterpret_cast<const __half2*>(&r1.x);
        hk[5] = *reinterpret_cast<const __half2*>(&r1.y);
        hk[6] = *reinterpret_cast<const __half2*>(&r1.z);
        hk[7] = *reinterpret_cast<const __half2*>(&r1.w);
    };

#pragma unroll 1
    for (int t4i = 0; t4i < NT/4 - 1; t4i++) {
        const float4 nx0 = p0[t4i + 1];
        const float4 nx1 = p1[t4i + 1];
        const float4 nx2 = p2[t4i + 1];
        step(cx0.y, cx1.y, cx2.y, 0);
        step(cx0.z, cx1.z, cx2.z, 1);
        step(cx0.w, cx1.w, cx2.w, 0);
        step(nx0.x, nx1.x, nx2.x, 1);
        cx0 = nx0; cx1 = nx1; cx2 = nx2;
    }
    // last group: next-x args are don't-cares (reuse current)
    step(cx0.y, cx1.y, cx2.y, 0);
    step(cx0.z, cx1.z, cx2.z, 1);
    step(cx0.w, cx1.w, cx2.w, 0);
    step(cx0.w, cx1.w, cx2.w, 1);

    g_hlast[asset * NH + q] = h1;                 // units 0..15
    if (q < 4) g_hlast[asset * NH + 16 + q] = h2; // units 16..19
}

// head: fc + 1x1 conv compose linearly: z_b = cw0*la_b + relu(h_b)·u + s
__global__ void __launch_bounds__(NB)
head_kernel(const float* __restrict__ la,
            const float* __restrict__ fcw,
            const float* __restrict__ fcb,
            const float* __restrict__ cw,
            const float* __restrict__ cb,
            float* __restrict__ out)
{
    const int b = threadIdx.x;
    __shared__ float s_u[NH];
    __shared__ float s_s;
    __shared__ float s_red[32];
    __shared__ float s_bcast;

    if (b < NH) {
        float u = 0.f;
#pragma unroll
        for (int j = 0; j < NH; j++) u = fmaf(cw[1 + j], fcw[j * NH + b], u);
        s_u[b] = u;
    }
    if (b == NH) {
        float s = cb[0];
#pragma unroll
        for (int j = 0; j < NH; j++) s = fmaf(cw[1 + j], fcb[j], s);
        s_s = s;
    }
    __syncthreads();

    float z = fmaf(cw[0], la[b], s_s);
    const float* h = &g_hlast[b * NH];
#pragma unroll
    for (int j = 0; j < NH; j++) z = fmaf(fmaxf(h[j], 0.f), s_u[j], z);

    float m = z;
#pragma unroll
    for (int off = 16; off > 0; off >>= 1)
        m = fmaxf(m, __shfl_xor_sync(0xffffffffu, m, off));
    if ((b & 31) == 0) s_red[b >> 5] = m;
    __syncthreads();
    if (b < 32) {
        float v = s_red[b];
#pragma unroll
        for (int off = 16; off > 0; off >>= 1)
            v = fmaxf(v, __shfl_xor_sync(0xffffffffu, v, off));
        if (b == 0) s_bcast = fmaxf(v, 1.0f);
    }
    __syncthreads();
    m = s_bcast;

    float e = __expf(z - m);
    float s = e;
#pragma unroll
    for (int off = 16; off > 0; off >>= 1)
        s += __shfl_xor_sync(0xffffffffu, s, off);
    if ((b & 31) == 0) s_red[b >> 5] = s;
    __syncthreads();
    if (b < 32) {
        float v = s_red[b];
#pragma unroll
        for (int off = 16; off > 0; off >>= 1)
            v += __shfl_xor_sync(0xffffffffu, v, off);
        if (b == 0) s_bcast = v + __expf(1.0f - m);
    }
    __syncthreads();
    const float denom = s_bcast;

    out[1 + b] = e / denom;
    if (b == 0) out[0] = __expf(1.0f - m) / denom;
}

extern "C" void kernel_launch(void* const* d_in, const int* in_sizes, int n_in,
                              void* d_out, int out_size)
{
    const float* x   = (const float*)d_in[0];
    const float* la  = (const float*)d_in[1];
    const float* Wih = (const float*)d_in[2];
    const float* Whh = (const float*)d_in[3];
    const float* bih = (const float*)d_in[4];
    const float* bhh = (const float*)d_in[5];
    const float* fcw = (const float*)d_in[6];
    const float* fcb = (const float*)d_in[7];
    const float* cw  = (const float*)d_in[8];
    const float* cb  = (const float*)d_in[9];

    lstm_kernel<<<NB / 2, 32>>>(x, Wih, Whh, bih, bhh);
    head_kernel<<<1, NB>>>(la, fcw, fcb, cw, cb, (float*)d_out);
}